// round 10
// baseline (speedup 1.0000x reference)
#include <cuda_runtime.h>
#include <cuda_fp16.h>
#include <mma.h>

using namespace nvcuda;

#define N_NODES 50000
#define N_EDGES 800000
#define HIDDEN 128
#define NUM_GRAPHS 64
#define NUM_CLASSES 6

#define SCAN_BLK 256
#define SCAN_NBLK ((N_NODES + SCAN_BLK - 1) / SCAN_BLK)   // 196

// ---- scratch (static device globals; no runtime allocation) ----
__device__ __half2 g_hw2[N_NODES * (HIDDEN / 2)];   // h @ W, fp16 packed
__device__ __half2 g_h2[N_NODES * (HIDDEN / 2)];    // layer activation, fp16 packed
__device__ float   g_hf[N_NODES * HIDDEN];          // last-layer activation, fp32
__device__ __half  g_Wh[3 * HIDDEN * HIDDEN];       // fp16 weights
__device__ float   g_dinv[N_NODES];
__device__ int     g_deg[N_NODES];
__device__ int     g_rowptr[N_NODES + 1];
__device__ int     g_cursor[N_NODES];
__device__ int2    g_csr[N_EDGES];                  // (src, w bits) packed
__device__ int     g_bsum[SCAN_NBLK];
__device__ float   g_pool[NUM_GRAPHS * HIDDEN];
__device__ float   g_cnt[NUM_GRAPHS];

// ---- fused init: cvt x -> fp16, cvt weights -> fp16, zero deg/pool/cnt ----
__global__ void k_init(const float* __restrict__ x, const float* __restrict__ W0,
                       const float* __restrict__ W1, const float* __restrict__ W2) {
    int i = blockIdx.x * blockDim.x + threadIdx.x;
    if (i < N_NODES * (HIDDEN / 2)) {
        float2 v = ((const float2*)x)[i];
        g_h2[i] = __floats2half2_rn(v.x, v.y);
    }
    if (i < HIDDEN * HIDDEN) {
        g_Wh[i] = __float2half(W0[i]);
        g_Wh[HIDDEN * HIDDEN + i] = __float2half(W1[i]);
        g_Wh[2 * HIDDEN * HIDDEN + i] = __float2half(W2[i]);
    }
    if (i < N_NODES) g_deg[i] = 0;
    if (i < NUM_GRAPHS * HIDDEN) g_pool[i] = 0.f;
    if (i < NUM_GRAPHS) g_cnt[i] = 0.f;
}

__global__ void k_deg(const int* __restrict__ dst) {
    int e = blockIdx.x * blockDim.x + threadIdx.x;
    if (e < N_EDGES) atomicAdd(&g_deg[dst[e]], 1);
}

// ---- scan pass 1: per-block sums of g_deg ----
__global__ void k_scan1() {
    __shared__ int wsum[SCAN_BLK / 32];
    int i = blockIdx.x * SCAN_BLK + threadIdx.x;
    int v = (i < N_NODES) ? g_deg[i] : 0;
#pragma unroll
    for (int o = 16; o > 0; o >>= 1) v += __shfl_down_sync(0xffffffffu, v, o);
    if ((threadIdx.x & 31) == 0) wsum[threadIdx.x >> 5] = v;
    __syncthreads();
    if (threadIdx.x < SCAN_BLK / 32) {
        int s = wsum[threadIdx.x];
#pragma unroll
        for (int o = SCAN_BLK / 64; o > 0; o >>= 1)
            s += __shfl_down_sync(0xffffffffu, s, o);
        if (threadIdx.x == 0) g_bsum[blockIdx.x] = s;
    }
}

// ---- scan pass 2: per-block local scan; block offset computed inline ----
__global__ void k_scan3() {
    __shared__ int wpre[SCAN_BLK / 32];
    __shared__ int s_off;
    int lane = threadIdx.x & 31;
    int wid = threadIdx.x >> 5;

    // block offset = sum of g_bsum[0 .. blockIdx.x)
    int partial = 0;
    for (int b = threadIdx.x; b < blockIdx.x; b += SCAN_BLK)
        partial += g_bsum[b];
#pragma unroll
    for (int o = 16; o > 0; o >>= 1)
        partial += __shfl_down_sync(0xffffffffu, partial, o);
    if (lane == 0) wpre[wid] = partial;
    __syncthreads();
    if (threadIdx.x == 0) {
        int s = 0;
#pragma unroll
        for (int w = 0; w < SCAN_BLK / 32; w++) s += wpre[w];
        s_off = s;
    }
    __syncthreads();

    int i = blockIdx.x * SCAN_BLK + threadIdx.x;
    int v = (i < N_NODES) ? g_deg[i] : 0;
    int x = v;
#pragma unroll
    for (int o = 1; o < 32; o <<= 1) {
        int y = __shfl_up_sync(0xffffffffu, x, o);
        if (lane >= o) x += y;
    }
    if (lane == 31) wpre[wid] = x;
    __syncthreads();
    if (wid == 0 && lane < SCAN_BLK / 32) {
        int s = wpre[lane];
#pragma unroll
        for (int o = 1; o < SCAN_BLK / 32; o <<= 1) {
            int y = __shfl_up_sync((1u << (SCAN_BLK / 32)) - 1u, s, o);
            if (lane >= o) s += y;
        }
        wpre[lane] = s;
    }
    __syncthreads();
    if (i < N_NODES) {
        int excl = (x - v) + (wid > 0 ? wpre[wid - 1] : 0) + s_off;
        g_rowptr[i] = excl;
        g_cursor[i] = excl;
        g_dinv[i] = rsqrtf((float)(v + 1));   // +1 self-loop
        if (i == 0) g_rowptr[N_NODES] = N_EDGES;
    }
}

// ---- fill CSR (packed src + weight), bucketed by dst ----
__global__ void k_fill(const int* __restrict__ src, const int* __restrict__ dst) {
    int e = blockIdx.x * blockDim.x + threadIdx.x;
    if (e >= N_EDGES) return;
    int s = src[e];
    int d = dst[e];
    int pos = atomicAdd(&g_cursor[d], 1);
    float w = g_dinv[s] * g_dinv[d];
    g_csr[pos] = make_int2(s, __float_as_int(w));
}

// ---- tensor-core projection: hw = h @ W (fp16 in, fp32 accum, fp16 out) ----
#define TC_ROWS 64
__global__ void __launch_bounds__(256) k_gemm_tc(int layer) {
    __shared__ __align__(256) char smem_raw[TC_ROWS * HIDDEN * 4];  // 32 KB
    __half* sB = (__half*)smem_raw;       // phase 1: B tile 128x128 fp16
    float*  sC = (float*)smem_raw;        // phase 2: C staging 64x128 fp32
    int tid = threadIdx.x;

    const int4* Bv = (const int4*)(g_Wh + (size_t)layer * HIDDEN * HIDDEN);
    int4* sBv = (int4*)sB;
#pragma unroll
    for (int i = 0; i < 8; i++)
        sBv[tid + i * 256] = Bv[tid + i * 256];
    __syncthreads();

    int warp = tid >> 5;
    int rt = warp >> 1;       // 0..3
    int ch = warp & 1;        // 0..1
    int row0 = blockIdx.x * TC_ROWS + rt * 16;
    bool active = row0 < N_NODES;   // warp-uniform

    wmma::fragment<wmma::accumulator, 16, 16, 16, float> c[4];
#pragma unroll
    for (int j = 0; j < 4; j++) wmma::fill_fragment(c[j], 0.f);

    if (active) {
        const __half* A = (const __half*)g_h2;
#pragma unroll
        for (int k = 0; k < 8; k++) {
            wmma::fragment<wmma::matrix_a, 16, 16, 16, __half, wmma::row_major> a;
            wmma::load_matrix_sync(a, A + (size_t)row0 * HIDDEN + k * 16, HIDDEN);
#pragma unroll
            for (int j = 0; j < 4; j++) {
                wmma::fragment<wmma::matrix_b, 16, 16, 16, __half, wmma::row_major> b;
                wmma::load_matrix_sync(b, sB + (k * 16) * HIDDEN + ch * 64 + j * 16, HIDDEN);
                wmma::mma_sync(c[j], a, b, c[j]);
            }
        }
    }
    __syncthreads();
    if (active) {
#pragma unroll
        for (int j = 0; j < 4; j++)
            wmma::store_matrix_sync(sC + (rt * 16) * HIDDEN + ch * 64 + j * 16,
                                    c[j], HIDDEN, wmma::mem_row_major);
    }
    __syncthreads();

    int row_base = blockIdx.x * TC_ROWS;
#pragma unroll
    for (int i = 0; i < 16; i++) {
        int idx = tid + i * 256;          // half2 slot in tile: 0..4095
        int r = idx >> 6;
        if (row_base + r < N_NODES) {
            float2 v = ((float2*)sC)[idx];
            g_hw2[(size_t)(row_base + r) * 64 + (idx & 63)] = __floats2half2_rn(v.x, v.y);
        }
    }
}

// ---- fused aggregate (CSR half2 gather) + self-loop + bias + ReLU ----
// last==0: write fp16 g_h2 (next GEMM); last==1: write fp32 g_hf (pool).
#define AGG_NODES 4
__global__ void k_agg(const float* __restrict__ bias, int last) {
    int n = blockIdx.x * AGG_NODES + (threadIdx.x >> 6);
    int t = threadIdx.x & 63;   // half2 column index (cols 2t, 2t+1)
    int beg = g_rowptr[n];
    int end = g_rowptr[n + 1];
    float dv = g_dinv[n];
    float2 self = __half22float2(g_hw2[(size_t)n * 64 + t]);
    float ax = dv * dv * self.x;
    float ay = dv * dv * self.y;
    int j = beg;
    for (; j + 4 <= end; j += 4) {
        int2 e0 = g_csr[j + 0], e1 = g_csr[j + 1];
        int2 e2 = g_csr[j + 2], e3 = g_csr[j + 3];
        float2 v0 = __half22float2(g_hw2[(size_t)e0.x * 64 + t]);
        float2 v1 = __half22float2(g_hw2[(size_t)e1.x * 64 + t]);
        float2 v2 = __half22float2(g_hw2[(size_t)e2.x * 64 + t]);
        float2 v3 = __half22float2(g_hw2[(size_t)e3.x * 64 + t]);
        float w0 = __int_as_float(e0.y), w1 = __int_as_float(e1.y);
        float w2 = __int_as_float(e2.y), w3 = __int_as_float(e3.y);
        ax += w0 * v0.x; ay += w0 * v0.y;
        ax += w1 * v1.x; ay += w1 * v1.y;
        ax += w2 * v2.x; ay += w2 * v2.y;
        ax += w3 * v3.x; ay += w3 * v3.y;
    }
    for (; j < end; j++) {
        int2 e = g_csr[j];
        float w = __int_as_float(e.y);
        float2 v = __half22float2(g_hw2[(size_t)e.x * 64 + t]);
        ax += w * v.x; ay += w * v.y;
    }
    float2 b = ((const float2*)bias)[t];
    float rx = fmaxf(ax + b.x, 0.f);
    float ry = fmaxf(ay + b.y, 0.f);
    if (last)
        ((float2*)g_hf)[(size_t)n * 64 + t] = make_float2(rx, ry);
    else
        g_h2[(size_t)n * 64 + t] = __floats2half2_rn(rx, ry);
}

// ---- pooling: run-length accumulate over sorted batch ids (fp32 h) ----
#define NODES_PER_BLOCK 32
__global__ void k_pool(const int* __restrict__ batch) {
    int n0 = blockIdx.x * NODES_PER_BLOCK;
    if (n0 >= N_NODES) return;
    int t = threadIdx.x;  // 0..63, float2 column pair
    int cur = batch[n0];
    float ax = 0.f, ay = 0.f;
    int run = 0;
    for (int r = 0; r < NODES_PER_BLOCK; r++) {
        int n = n0 + r;
        if (n >= N_NODES) break;
        int bg = batch[n];
        if (bg != cur) {
            atomicAdd(&g_pool[cur * HIDDEN + 2 * t], ax);
            atomicAdd(&g_pool[cur * HIDDEN + 2 * t + 1], ay);
            if (t == 0) atomicAdd(&g_cnt[cur], (float)run);
            ax = 0.f; ay = 0.f; run = 0; cur = bg;
        }
        float2 v = ((const float2*)g_hf)[(size_t)n * 64 + t];
        ax += v.x; ay += v.y;
        run++;
    }
    atomicAdd(&g_pool[cur * HIDDEN + 2 * t], ax);
    atomicAdd(&g_pool[cur * HIDDEN + 2 * t + 1], ay);
    if (t == 0) atomicAdd(&g_cnt[cur], (float)run);
}

// ---- mean + linear head, write outputs ----
__global__ void k_final(const float* __restrict__ linW, const float* __restrict__ linb,
                        float* __restrict__ out, int emb_off,
                        int write_emb, int write_logits) {
    int g = blockIdx.x;
    int t = threadIdx.x;  // 128
    float c = fmaxf(g_cnt[g], 1.f);
    float e = g_pool[g * HIDDEN + t] / c;
    __shared__ float se[HIDDEN];
    se[t] = e;
    if (write_emb) out[emb_off + g * HIDDEN + t] = e;
    __syncthreads();
    if (write_logits && t < NUM_CLASSES) {
        float acc = linb[t];
#pragma unroll 16
        for (int k = 0; k < HIDDEN; k++)
            acc += se[k] * linW[k * NUM_CLASSES + t];
        out[g * NUM_CLASSES + t] = acc;
    }
}

extern "C" void kernel_launch(void* const* d_in, const int* in_sizes, int n_in,
                              void* d_out, int out_size) {
    const float* x     = (const float*)d_in[0];
    const int*   ei    = (const int*)d_in[1];   // [2, E] (JAX x64 off -> int32)
    const int*   batch = (const int*)d_in[2];
    const float* W0 = (const float*)d_in[3];
    const float* b0 = (const float*)d_in[4];
    const float* W1 = (const float*)d_in[5];
    const float* b1 = (const float*)d_in[6];
    const float* W2 = (const float*)d_in[7];
    const float* b2 = (const float*)d_in[8];
    const float* linW = (const float*)d_in[9];
    const float* linb = (const float*)d_in[10];
    float* out = (float*)d_out;

    const int* src = ei;            // edge_index[0]
    const int* dst = ei + N_EDGES;  // edge_index[1]

    // ---- fused init + CSR build (once per launch) ----
    k_init<<<(N_NODES * (HIDDEN / 2) + 255) / 256, 256>>>(x, W0, W1, W2);
    k_deg<<<(N_EDGES + 255) / 256, 256>>>(dst);
    k_scan1<<<SCAN_NBLK, SCAN_BLK>>>();
    k_scan3<<<SCAN_NBLK, SCAN_BLK>>>();
    k_fill<<<(N_EDGES + 255) / 256, 256>>>(src, dst);

    const float* bs[3] = {b0, b1, b2};
    const int gemm_grid = (N_NODES + TC_ROWS - 1) / TC_ROWS;   // 782
    const int agg_grid = N_NODES / AGG_NODES;                  // 12500 exact

    for (int l = 0; l < 3; l++) {
        k_gemm_tc<<<gemm_grid, 256>>>(l);
        k_agg<<<agg_grid, 256>>>(bs[l], l == 2);
    }

    k_pool<<<(N_NODES + NODES_PER_BLOCK - 1) / NODES_PER_BLOCK, 64>>>(batch);

    // Output: reference returns (logits[64,6], embedding[64,128]) -> 8576 floats.
    int write_logits = 1, write_emb = 0, emb_off = 0;
    if (out_size >= NUM_GRAPHS * (NUM_CLASSES + HIDDEN)) {
        write_emb = 1; emb_off = NUM_GRAPHS * NUM_CLASSES;
    } else if (out_size == NUM_GRAPHS * HIDDEN) {
        write_emb = 1; write_logits = 0; emb_off = 0;
    }
    k_final<<<NUM_GRAPHS, HIDDEN>>>(linW, linb, out, emb_off, write_emb, write_logits);
}

// round 11
// speedup vs baseline: 1.2327x; 1.2327x over previous
#include <cuda_runtime.h>
#include <cuda_fp16.h>
#include <mma.h>

using namespace nvcuda;

#define N_NODES 50000
#define N_EDGES 800000
#define HIDDEN 128
#define NUM_GRAPHS 64
#define NUM_CLASSES 6

#define SCAN_BLK 256
#define SCAN_NBLK ((N_NODES + SCAN_BLK - 1) / SCAN_BLK)   // 196

// ---- scratch (static device globals; no runtime allocation) ----
__device__ __half2 g_hw2[N_NODES * (HIDDEN / 2)];   // h @ W, fp16 packed
__device__ __half2 g_h2[N_NODES * (HIDDEN / 2)];    // layer activation, fp16 packed
__device__ __half  g_Wh[3 * HIDDEN * HIDDEN];       // fp16 weights
__device__ float   g_dinv[N_NODES];
__device__ int     g_deg[N_NODES];
__device__ int     g_rowptr[N_NODES + 1];
__device__ int     g_cursor[N_NODES];
__device__ int2    g_csr[N_EDGES];                  // (src, w bits) packed
__device__ int     g_bsum[SCAN_NBLK];
__device__ float   g_pool[NUM_GRAPHS * HIDDEN];
__device__ float   g_cnt[NUM_GRAPHS];

// ---- fused init: cvt x -> fp16, cvt weights -> fp16, zero deg/pool/cnt ----
__global__ void k_init(const float* __restrict__ x, const float* __restrict__ W0,
                       const float* __restrict__ W1, const float* __restrict__ W2) {
    int i = blockIdx.x * blockDim.x + threadIdx.x;
    if (i < N_NODES * (HIDDEN / 2)) {
        float2 v = ((const float2*)x)[i];
        g_h2[i] = __floats2half2_rn(v.x, v.y);
    }
    if (i < HIDDEN * HIDDEN) {
        g_Wh[i] = __float2half(W0[i]);
        g_Wh[HIDDEN * HIDDEN + i] = __float2half(W1[i]);
        g_Wh[2 * HIDDEN * HIDDEN + i] = __float2half(W2[i]);
    }
    if (i < N_NODES) g_deg[i] = 0;
    if (i < NUM_GRAPHS * HIDDEN) g_pool[i] = 0.f;
    if (i < NUM_GRAPHS) g_cnt[i] = 0.f;
}

__global__ void k_deg(const int* __restrict__ dst) {
    int e = blockIdx.x * blockDim.x + threadIdx.x;
    if (e < N_EDGES) atomicAdd(&g_deg[dst[e]], 1);
}

// ---- scan pass 1: per-block sums of g_deg ----
__global__ void k_scan1() {
    __shared__ int wsum[SCAN_BLK / 32];
    int i = blockIdx.x * SCAN_BLK + threadIdx.x;
    int v = (i < N_NODES) ? g_deg[i] : 0;
#pragma unroll
    for (int o = 16; o > 0; o >>= 1) v += __shfl_down_sync(0xffffffffu, v, o);
    if ((threadIdx.x & 31) == 0) wsum[threadIdx.x >> 5] = v;
    __syncthreads();
    if (threadIdx.x < SCAN_BLK / 32) {
        int s = wsum[threadIdx.x];
#pragma unroll
        for (int o = SCAN_BLK / 64; o > 0; o >>= 1)
            s += __shfl_down_sync(0xffffffffu, s, o);
        if (threadIdx.x == 0) g_bsum[blockIdx.x] = s;
    }
}

// ---- scan pass 2: per-block local scan; block offset computed inline ----
__global__ void k_scan3() {
    __shared__ int wpre[SCAN_BLK / 32];
    __shared__ int s_off;
    int lane = threadIdx.x & 31;
    int wid = threadIdx.x >> 5;

    // block offset = sum of g_bsum[0 .. blockIdx.x)
    int partial = 0;
    for (int b = threadIdx.x; b < blockIdx.x; b += SCAN_BLK)
        partial += g_bsum[b];
#pragma unroll
    for (int o = 16; o > 0; o >>= 1)
        partial += __shfl_down_sync(0xffffffffu, partial, o);
    if (lane == 0) wpre[wid] = partial;
    __syncthreads();
    if (threadIdx.x == 0) {
        int s = 0;
#pragma unroll
        for (int w = 0; w < SCAN_BLK / 32; w++) s += wpre[w];
        s_off = s;
    }
    __syncthreads();

    int i = blockIdx.x * SCAN_BLK + threadIdx.x;
    int v = (i < N_NODES) ? g_deg[i] : 0;
    int x = v;
#pragma unroll
    for (int o = 1; o < 32; o <<= 1) {
        int y = __shfl_up_sync(0xffffffffu, x, o);
        if (lane >= o) x += y;
    }
    if (lane == 31) wpre[wid] = x;
    __syncthreads();
    if (wid == 0 && lane < SCAN_BLK / 32) {
        int s = wpre[lane];
#pragma unroll
        for (int o = 1; o < SCAN_BLK / 32; o <<= 1) {
            int y = __shfl_up_sync((1u << (SCAN_BLK / 32)) - 1u, s, o);
            if (lane >= o) s += y;
        }
        wpre[lane] = s;
    }
    __syncthreads();
    if (i < N_NODES) {
        int excl = (x - v) + (wid > 0 ? wpre[wid - 1] : 0) + s_off;
        g_rowptr[i] = excl;
        g_cursor[i] = excl;
        g_dinv[i] = rsqrtf((float)(v + 1));   // +1 self-loop
        if (i == 0) g_rowptr[N_NODES] = N_EDGES;
    }
}

// ---- fill CSR (packed src + weight), bucketed by dst ----
__global__ void k_fill(const int* __restrict__ src, const int* __restrict__ dst) {
    int e = blockIdx.x * blockDim.x + threadIdx.x;
    if (e >= N_EDGES) return;
    int s = src[e];
    int d = dst[e];
    int pos = atomicAdd(&g_cursor[d], 1);
    float w = g_dinv[s] * g_dinv[d];
    g_csr[pos] = make_int2(s, __float_as_int(w));
}

// ---- tensor-core projection: hw = h @ W (fp16 in, fp32 accum, fp16 out) ----
#define TC_ROWS 64
__global__ void __launch_bounds__(256) k_gemm_tc(int layer) {
    __shared__ __align__(256) char smem_raw[TC_ROWS * HIDDEN * 4];  // 32 KB
    __half* sB = (__half*)smem_raw;       // phase 1: B tile 128x128 fp16
    float*  sC = (float*)smem_raw;        // phase 2: C staging 64x128 fp32
    int tid = threadIdx.x;

    const int4* Bv = (const int4*)(g_Wh + (size_t)layer * HIDDEN * HIDDEN);
    int4* sBv = (int4*)sB;
#pragma unroll
    for (int i = 0; i < 8; i++)
        sBv[tid + i * 256] = Bv[tid + i * 256];
    __syncthreads();

    int warp = tid >> 5;
    int rt = warp >> 1;       // 0..3
    int ch = warp & 1;        // 0..1
    int row0 = blockIdx.x * TC_ROWS + rt * 16;
    bool active = row0 < N_NODES;   // warp-uniform

    wmma::fragment<wmma::accumulator, 16, 16, 16, float> c[4];
#pragma unroll
    for (int j = 0; j < 4; j++) wmma::fill_fragment(c[j], 0.f);

    if (active) {
        const __half* A = (const __half*)g_h2;
#pragma unroll
        for (int k = 0; k < 8; k++) {
            wmma::fragment<wmma::matrix_a, 16, 16, 16, __half, wmma::row_major> a;
            wmma::load_matrix_sync(a, A + (size_t)row0 * HIDDEN + k * 16, HIDDEN);
#pragma unroll
            for (int j = 0; j < 4; j++) {
                wmma::fragment<wmma::matrix_b, 16, 16, 16, __half, wmma::row_major> b;
                wmma::load_matrix_sync(b, sB + (k * 16) * HIDDEN + ch * 64 + j * 16, HIDDEN);
                wmma::mma_sync(c[j], a, b, c[j]);
            }
        }
    }
    __syncthreads();
    if (active) {
#pragma unroll
        for (int j = 0; j < 4; j++)
            wmma::store_matrix_sync(sC + (rt * 16) * HIDDEN + ch * 64 + j * 16,
                                    c[j], HIDDEN, wmma::mem_row_major);
    }
    __syncthreads();

    int row_base = blockIdx.x * TC_ROWS;
#pragma unroll
    for (int i = 0; i < 16; i++) {
        int idx = tid + i * 256;          // half2 slot in tile: 0..4095
        int r = idx >> 6;
        if (row_base + r < N_NODES) {
            float2 v = ((float2*)sC)[idx];
            g_hw2[(size_t)(row_base + r) * 64 + (idx & 63)] = __floats2half2_rn(v.x, v.y);
        }
    }
}

// ---- fused aggregate: 1 warp per node, 8B (2x half2) per thread ----
#define AGG_NODES 8
__global__ void k_agg(const float* __restrict__ bias) {
    int n = blockIdx.x * AGG_NODES + (threadIdx.x >> 5);
    int t = threadIdx.x & 31;   // uint2 slot: half2 pair (cols 4t..4t+3)
    int beg = g_rowptr[n];
    int end = g_rowptr[n + 1];
    float dv = g_dinv[n];

    const uint2* hw = (const uint2*)g_hw2;   // 32 uint2 per row
    uint2 sr = hw[(size_t)n * 32 + t];
    float2 s0 = __half22float2(*(__half2*)&sr.x);
    float2 s1 = __half22float2(*(__half2*)&sr.y);
    float n2 = dv * dv;
    float ax = n2 * s0.x, ay = n2 * s0.y;
    float az = n2 * s1.x, aw = n2 * s1.y;

    int j = beg;
    for (; j + 4 <= end; j += 4) {
        int2 e0 = g_csr[j + 0], e1 = g_csr[j + 1];
        int2 e2 = g_csr[j + 2], e3 = g_csr[j + 3];
        uint2 r0 = hw[(size_t)e0.x * 32 + t];
        uint2 r1 = hw[(size_t)e1.x * 32 + t];
        uint2 r2 = hw[(size_t)e2.x * 32 + t];
        uint2 r3 = hw[(size_t)e3.x * 32 + t];
        float w0 = __int_as_float(e0.y), w1 = __int_as_float(e1.y);
        float w2 = __int_as_float(e2.y), w3 = __int_as_float(e3.y);
        float2 a0 = __half22float2(*(__half2*)&r0.x), b0 = __half22float2(*(__half2*)&r0.y);
        float2 a1 = __half22float2(*(__half2*)&r1.x), b1 = __half22float2(*(__half2*)&r1.y);
        float2 a2 = __half22float2(*(__half2*)&r2.x), b2 = __half22float2(*(__half2*)&r2.y);
        float2 a3 = __half22float2(*(__half2*)&r3.x), b3 = __half22float2(*(__half2*)&r3.y);
        ax += w0 * a0.x; ay += w0 * a0.y; az += w0 * b0.x; aw += w0 * b0.y;
        ax += w1 * a1.x; ay += w1 * a1.y; az += w1 * b1.x; aw += w1 * b1.y;
        ax += w2 * a2.x; ay += w2 * a2.y; az += w2 * b2.x; aw += w2 * b2.y;
        ax += w3 * a3.x; ay += w3 * a3.y; az += w3 * b3.x; aw += w3 * b3.y;
    }
    for (; j < end; j++) {
        int2 e = g_csr[j];
        float w = __int_as_float(e.y);
        uint2 r = hw[(size_t)e.x * 32 + t];
        float2 a = __half22float2(*(__half2*)&r.x);
        float2 b = __half22float2(*(__half2*)&r.y);
        ax += w * a.x; ay += w * a.y; az += w * b.x; aw += w * b.y;
    }
    float4 b4 = ((const float4*)bias)[t];
    uint2 outp;
    *(__half2*)&outp.x = __floats2half2_rn(fmaxf(ax + b4.x, 0.f), fmaxf(ay + b4.y, 0.f));
    *(__half2*)&outp.y = __floats2half2_rn(fmaxf(az + b4.z, 0.f), fmaxf(aw + b4.w, 0.f));
    ((uint2*)g_h2)[(size_t)n * 32 + t] = outp;
}

// ---- pooling: run-length accumulate over sorted batch ids (fp16 h, fp32 acc) ----
#define NODES_PER_BLOCK 32
__global__ void k_pool(const int* __restrict__ batch) {
    int n0 = blockIdx.x * NODES_PER_BLOCK;
    if (n0 >= N_NODES) return;
    int t = threadIdx.x;  // 0..63, half2 column pair
    int cur = batch[n0];
    float ax = 0.f, ay = 0.f;
    int run = 0;
    for (int r = 0; r < NODES_PER_BLOCK; r++) {
        int n = n0 + r;
        if (n >= N_NODES) break;
        int bg = batch[n];
        if (bg != cur) {
            atomicAdd(&g_pool[cur * HIDDEN + 2 * t], ax);
            atomicAdd(&g_pool[cur * HIDDEN + 2 * t + 1], ay);
            if (t == 0) atomicAdd(&g_cnt[cur], (float)run);
            ax = 0.f; ay = 0.f; run = 0; cur = bg;
        }
        float2 v = __half22float2(g_h2[(size_t)n * 64 + t]);
        ax += v.x; ay += v.y;
        run++;
    }
    atomicAdd(&g_pool[cur * HIDDEN + 2 * t], ax);
    atomicAdd(&g_pool[cur * HIDDEN + 2 * t + 1], ay);
    if (t == 0) atomicAdd(&g_cnt[cur], (float)run);
}

// ---- mean + linear head, write outputs ----
__global__ void k_final(const float* __restrict__ linW, const float* __restrict__ linb,
                        float* __restrict__ out, int emb_off,
                        int write_emb, int write_logits) {
    int g = blockIdx.x;
    int t = threadIdx.x;  // 128
    float c = fmaxf(g_cnt[g], 1.f);
    float e = g_pool[g * HIDDEN + t] / c;
    __shared__ float se[HIDDEN];
    se[t] = e;
    if (write_emb) out[emb_off + g * HIDDEN + t] = e;
    __syncthreads();
    if (write_logits && t < NUM_CLASSES) {
        float acc = linb[t];
#pragma unroll 16
        for (int k = 0; k < HIDDEN; k++)
            acc += se[k] * linW[k * NUM_CLASSES + t];
        out[g * NUM_CLASSES + t] = acc;
    }
}

extern "C" void kernel_launch(void* const* d_in, const int* in_sizes, int n_in,
                              void* d_out, int out_size) {
    const float* x     = (const float*)d_in[0];
    const int*   ei    = (const int*)d_in[1];   // [2, E] (JAX x64 off -> int32)
    const int*   batch = (const int*)d_in[2];
    const float* W0 = (const float*)d_in[3];
    const float* b0 = (const float*)d_in[4];
    const float* W1 = (const float*)d_in[5];
    const float* b1 = (const float*)d_in[6];
    const float* W2 = (const float*)d_in[7];
    const float* b2 = (const float*)d_in[8];
    const float* linW = (const float*)d_in[9];
    const float* linb = (const float*)d_in[10];
    float* out = (float*)d_out;

    const int* src = ei;            // edge_index[0]
    const int* dst = ei + N_EDGES;  // edge_index[1]

    // ---- fused init + CSR build (once per launch) ----
    k_init<<<(N_NODES * (HIDDEN / 2) + 255) / 256, 256>>>(x, W0, W1, W2);
    k_deg<<<(N_EDGES + 255) / 256, 256>>>(dst);
    k_scan1<<<SCAN_NBLK, SCAN_BLK>>>();
    k_scan3<<<SCAN_NBLK, SCAN_BLK>>>();
    k_fill<<<(N_EDGES + 255) / 256, 256>>>(src, dst);

    const float* bs[3] = {b0, b1, b2};
    const int gemm_grid = (N_NODES + TC_ROWS - 1) / TC_ROWS;   // 782
    const int agg_grid = (N_NODES + AGG_NODES - 1) / AGG_NODES;  // 6250 exact

    for (int l = 0; l < 3; l++) {
        k_gemm_tc<<<gemm_grid, 256>>>(l);
        k_agg<<<agg_grid, 256>>>(bs[l]);
    }

    k_pool<<<(N_NODES + NODES_PER_BLOCK - 1) / NODES_PER_BLOCK, 64>>>(batch);

    // Output: reference returns (logits[64,6], embedding[64,128]) -> 8576 floats.
    int write_logits = 1, write_emb = 0, emb_off = 0;
    if (out_size >= NUM_GRAPHS * (NUM_CLASSES + HIDDEN)) {
        write_emb = 1; emb_off = NUM_GRAPHS * NUM_CLASSES;
    } else if (out_size == NUM_GRAPHS * HIDDEN) {
        write_emb = 1; write_logits = 0; emb_off = 0;
    }
    k_final<<<NUM_GRAPHS, HIDDEN>>>(linW, linb, out, emb_off, write_emb, write_logits);
}

// round 12
// speedup vs baseline: 1.2778x; 1.0365x over previous
#include <cuda_runtime.h>
#include <cuda_fp16.h>
#include <mma.h>

using namespace nvcuda;

#define N_NODES 50000
#define N_EDGES 800000
#define HIDDEN 128
#define NUM_GRAPHS 64
#define NUM_CLASSES 6

#define SCAN_BLK 256
#define SCAN_NBLK ((N_NODES + SCAN_BLK - 1) / SCAN_BLK)   // 196

// ---- scratch (static device globals; no runtime allocation) ----
__device__ __half2 g_hw2[N_NODES * (HIDDEN / 2)];   // h @ W, fp16 packed
__device__ __half2 g_h2[N_NODES * (HIDDEN / 2)];    // layer activation, fp16 packed
__device__ __half  g_Wh[3 * HIDDEN * HIDDEN];       // fp16 weights
__device__ float   g_dinv[N_NODES];
__device__ int     g_deg[N_NODES];
__device__ int     g_rowptr[N_NODES + 1];
__device__ int     g_cursor[N_NODES];
__device__ int2    g_csr[N_EDGES];                  // (src, w bits) packed
__device__ int     g_bsum[SCAN_NBLK];
__device__ float   g_pool[NUM_GRAPHS * HIDDEN];
__device__ float   g_cnt[NUM_GRAPHS];

// ---- branch-B head: zero degree array ----
__global__ void k_zerodeg() {
    int i = blockIdx.x * blockDim.x + threadIdx.x;
    if (i < N_NODES) g_deg[i] = 0;
}

// ---- branch-A: cvt x -> fp16, cvt weights -> fp16, zero pool/cnt ----
__global__ void k_init(const float* __restrict__ x, const float* __restrict__ W0,
                       const float* __restrict__ W1, const float* __restrict__ W2) {
    int i = blockIdx.x * blockDim.x + threadIdx.x;
    if (i < N_NODES * (HIDDEN / 2)) {
        float2 v = ((const float2*)x)[i];
        g_h2[i] = __floats2half2_rn(v.x, v.y);
    }
    if (i < HIDDEN * HIDDEN) {
        g_Wh[i] = __float2half(W0[i]);
        g_Wh[HIDDEN * HIDDEN + i] = __float2half(W1[i]);
        g_Wh[2 * HIDDEN * HIDDEN + i] = __float2half(W2[i]);
    }
    if (i < NUM_GRAPHS * HIDDEN) g_pool[i] = 0.f;
    if (i < NUM_GRAPHS) g_cnt[i] = 0.f;
}

// ---- degree histogram: 2 edges per thread ----
__global__ void k_deg(const int* __restrict__ dst) {
    int i = blockIdx.x * blockDim.x + threadIdx.x;
    if (2 * i + 1 < N_EDGES) {
        int2 d = ((const int2*)dst)[i];
        atomicAdd(&g_deg[d.x], 1);
        atomicAdd(&g_deg[d.y], 1);
    } else if (2 * i < N_EDGES) {
        atomicAdd(&g_deg[dst[2 * i]], 1);
    }
}

// ---- scan pass 1: per-block sums of g_deg ----
__global__ void k_scan1() {
    __shared__ int wsum[SCAN_BLK / 32];
    int i = blockIdx.x * SCAN_BLK + threadIdx.x;
    int v = (i < N_NODES) ? g_deg[i] : 0;
#pragma unroll
    for (int o = 16; o > 0; o >>= 1) v += __shfl_down_sync(0xffffffffu, v, o);
    if ((threadIdx.x & 31) == 0) wsum[threadIdx.x >> 5] = v;
    __syncthreads();
    if (threadIdx.x < SCAN_BLK / 32) {
        int s = wsum[threadIdx.x];
#pragma unroll
        for (int o = SCAN_BLK / 64; o > 0; o >>= 1)
            s += __shfl_down_sync(0xffffffffu, s, o);
        if (threadIdx.x == 0) g_bsum[blockIdx.x] = s;
    }
}

// ---- scan pass 2: per-block local scan; block offset computed inline ----
__global__ void k_scan3() {
    __shared__ int wpre[SCAN_BLK / 32];
    __shared__ int s_off;
    int lane = threadIdx.x & 31;
    int wid = threadIdx.x >> 5;

    // block offset = sum of g_bsum[0 .. blockIdx.x)
    int partial = 0;
    for (int b = threadIdx.x; b < blockIdx.x; b += SCAN_BLK)
        partial += g_bsum[b];
#pragma unroll
    for (int o = 16; o > 0; o >>= 1)
        partial += __shfl_down_sync(0xffffffffu, partial, o);
    if (lane == 0) wpre[wid] = partial;
    __syncthreads();
    if (threadIdx.x == 0) {
        int s = 0;
#pragma unroll
        for (int w = 0; w < SCAN_BLK / 32; w++) s += wpre[w];
        s_off = s;
    }
    __syncthreads();

    int i = blockIdx.x * SCAN_BLK + threadIdx.x;
    int v = (i < N_NODES) ? g_deg[i] : 0;
    int x = v;
#pragma unroll
    for (int o = 1; o < 32; o <<= 1) {
        int y = __shfl_up_sync(0xffffffffu, x, o);
        if (lane >= o) x += y;
    }
    if (lane == 31) wpre[wid] = x;
    __syncthreads();
    if (wid == 0 && lane < SCAN_BLK / 32) {
        int s = wpre[lane];
#pragma unroll
        for (int o = 1; o < SCAN_BLK / 32; o <<= 1) {
            int y = __shfl_up_sync((1u << (SCAN_BLK / 32)) - 1u, s, o);
            if (lane >= o) s += y;
        }
        wpre[lane] = s;
    }
    __syncthreads();
    if (i < N_NODES) {
        int excl = (x - v) + (wid > 0 ? wpre[wid - 1] : 0) + s_off;
        g_rowptr[i] = excl;
        g_cursor[i] = excl;
        g_dinv[i] = rsqrtf((float)(v + 1));   // +1 self-loop
        if (i == 0) g_rowptr[N_NODES] = N_EDGES;
    }
}

// ---- fill CSR (packed src + weight), bucketed by dst ----
__global__ void k_fill(const int* __restrict__ src, const int* __restrict__ dst) {
    int e = blockIdx.x * blockDim.x + threadIdx.x;
    if (e >= N_EDGES) return;
    int s = src[e];
    int d = dst[e];
    int pos = atomicAdd(&g_cursor[d], 1);
    float w = g_dinv[s] * g_dinv[d];
    g_csr[pos] = make_int2(s, __float_as_int(w));
}

// ---- tensor-core projection: hw = h @ W (fp16 in, fp32 accum, fp16 out) ----
#define TC_ROWS 64
__global__ void __launch_bounds__(256) k_gemm_tc(int layer) {
    __shared__ __align__(256) char smem_raw[TC_ROWS * HIDDEN * 4];  // 32 KB
    __half* sB = (__half*)smem_raw;       // phase 1: B tile 128x128 fp16
    float*  sC = (float*)smem_raw;        // phase 2: C staging 64x128 fp32
    int tid = threadIdx.x;

    const int4* Bv = (const int4*)(g_Wh + (size_t)layer * HIDDEN * HIDDEN);
    int4* sBv = (int4*)sB;
#pragma unroll
    for (int i = 0; i < 8; i++)
        sBv[tid + i * 256] = Bv[tid + i * 256];
    __syncthreads();

    int warp = tid >> 5;
    int rt = warp >> 1;       // 0..3
    int ch = warp & 1;        // 0..1
    int row0 = blockIdx.x * TC_ROWS + rt * 16;
    bool active = row0 < N_NODES;   // warp-uniform

    wmma::fragment<wmma::accumulator, 16, 16, 16, float> c[4];
#pragma unroll
    for (int j = 0; j < 4; j++) wmma::fill_fragment(c[j], 0.f);

    if (active) {
        const __half* A = (const __half*)g_h2;
#pragma unroll
        for (int k = 0; k < 8; k++) {
            wmma::fragment<wmma::matrix_a, 16, 16, 16, __half, wmma::row_major> a;
            wmma::load_matrix_sync(a, A + (size_t)row0 * HIDDEN + k * 16, HIDDEN);
#pragma unroll
            for (int j = 0; j < 4; j++) {
                wmma::fragment<wmma::matrix_b, 16, 16, 16, __half, wmma::row_major> b;
                wmma::load_matrix_sync(b, sB + (k * 16) * HIDDEN + ch * 64 + j * 16, HIDDEN);
                wmma::mma_sync(c[j], a, b, c[j]);
            }
        }
    }
    __syncthreads();
    if (active) {
#pragma unroll
        for (int j = 0; j < 4; j++)
            wmma::store_matrix_sync(sC + (rt * 16) * HIDDEN + ch * 64 + j * 16,
                                    c[j], HIDDEN, wmma::mem_row_major);
    }
    __syncthreads();

    int row_base = blockIdx.x * TC_ROWS;
#pragma unroll
    for (int i = 0; i < 16; i++) {
        int idx = tid + i * 256;          // half2 slot in tile: 0..4095
        int r = idx >> 6;
        if (row_base + r < N_NODES) {
            float2 v = ((float2*)sC)[idx];
            g_hw2[(size_t)(row_base + r) * 64 + (idx & 63)] = __floats2half2_rn(v.x, v.y);
        }
    }
}

// ---- fused aggregate: 1 warp per node, 8B (2x half2) per thread ----
#define AGG_NODES 8
__global__ void k_agg(const float* __restrict__ bias) {
    int n = blockIdx.x * AGG_NODES + (threadIdx.x >> 5);
    int t = threadIdx.x & 31;   // uint2 slot: half2 pair (cols 4t..4t+3)
    int beg = g_rowptr[n];
    int end = g_rowptr[n + 1];
    float dv = g_dinv[n];

    const uint2* hw = (const uint2*)g_hw2;   // 32 uint2 per row
    uint2 sr = hw[(size_t)n * 32 + t];
    float2 s0 = __half22float2(*(__half2*)&sr.x);
    float2 s1 = __half22float2(*(__half2*)&sr.y);
    float n2 = dv * dv;
    float ax = n2 * s0.x, ay = n2 * s0.y;
    float az = n2 * s1.x, aw = n2 * s1.y;

    int j = beg;
    for (; j + 4 <= end; j += 4) {
        int2 e0 = g_csr[j + 0], e1 = g_csr[j + 1];
        int2 e2 = g_csr[j + 2], e3 = g_csr[j + 3];
        uint2 r0 = hw[(size_t)e0.x * 32 + t];
        uint2 r1 = hw[(size_t)e1.x * 32 + t];
        uint2 r2 = hw[(size_t)e2.x * 32 + t];
        uint2 r3 = hw[(size_t)e3.x * 32 + t];
        float w0 = __int_as_float(e0.y), w1 = __int_as_float(e1.y);
        float w2 = __int_as_float(e2.y), w3 = __int_as_float(e3.y);
        float2 a0 = __half22float2(*(__half2*)&r0.x), b0 = __half22float2(*(__half2*)&r0.y);
        float2 a1 = __half22float2(*(__half2*)&r1.x), b1 = __half22float2(*(__half2*)&r1.y);
        float2 a2 = __half22float2(*(__half2*)&r2.x), b2 = __half22float2(*(__half2*)&r2.y);
        float2 a3 = __half22float2(*(__half2*)&r3.x), b3 = __half22float2(*(__half2*)&r3.y);
        ax += w0 * a0.x; ay += w0 * a0.y; az += w0 * b0.x; aw += w0 * b0.y;
        ax += w1 * a1.x; ay += w1 * a1.y; az += w1 * b1.x; aw += w1 * b1.y;
        ax += w2 * a2.x; ay += w2 * a2.y; az += w2 * b2.x; aw += w2 * b2.y;
        ax += w3 * a3.x; ay += w3 * a3.y; az += w3 * b3.x; aw += w3 * b3.y;
    }
    for (; j < end; j++) {
        int2 e = g_csr[j];
        float w = __int_as_float(e.y);
        uint2 r = hw[(size_t)e.x * 32 + t];
        float2 a = __half22float2(*(__half2*)&r.x);
        float2 b = __half22float2(*(__half2*)&r.y);
        ax += w * a.x; ay += w * a.y; az += w * b.x; aw += w * b.y;
    }
    float4 b4 = ((const float4*)bias)[t];
    uint2 outp;
    *(__half2*)&outp.x = __floats2half2_rn(fmaxf(ax + b4.x, 0.f), fmaxf(ay + b4.y, 0.f));
    *(__half2*)&outp.y = __floats2half2_rn(fmaxf(az + b4.z, 0.f), fmaxf(aw + b4.w, 0.f));
    ((uint2*)g_h2)[(size_t)n * 32 + t] = outp;
}

// ---- pooling: run-length accumulate over sorted batch ids (fp16 h, fp32 acc) ----
#define NODES_PER_BLOCK 32
__global__ void k_pool(const int* __restrict__ batch) {
    int n0 = blockIdx.x * NODES_PER_BLOCK;
    if (n0 >= N_NODES) return;
    int t = threadIdx.x;  // 0..63, half2 column pair
    int cur = batch[n0];
    float ax = 0.f, ay = 0.f;
    int run = 0;
    for (int r = 0; r < NODES_PER_BLOCK; r++) {
        int n = n0 + r;
        if (n >= N_NODES) break;
        int bg = batch[n];
        if (bg != cur) {
            atomicAdd(&g_pool[cur * HIDDEN + 2 * t], ax);
            atomicAdd(&g_pool[cur * HIDDEN + 2 * t + 1], ay);
            if (t == 0) atomicAdd(&g_cnt[cur], (float)run);
            ax = 0.f; ay = 0.f; run = 0; cur = bg;
        }
        float2 v = __half22float2(g_h2[(size_t)n * 64 + t]);
        ax += v.x; ay += v.y;
        run++;
    }
    atomicAdd(&g_pool[cur * HIDDEN + 2 * t], ax);
    atomicAdd(&g_pool[cur * HIDDEN + 2 * t + 1], ay);
    if (t == 0) atomicAdd(&g_cnt[cur], (float)run);
}

// ---- mean + linear head, write outputs ----
__global__ void k_final(const float* __restrict__ linW, const float* __restrict__ linb,
                        float* __restrict__ out, int emb_off,
                        int write_emb, int write_logits) {
    int g = blockIdx.x;
    int t = threadIdx.x;  // 128
    float c = fmaxf(g_cnt[g], 1.f);
    float e = g_pool[g * HIDDEN + t] / c;
    __shared__ float se[HIDDEN];
    se[t] = e;
    if (write_emb) out[emb_off + g * HIDDEN + t] = e;
    __syncthreads();
    if (write_logits && t < NUM_CLASSES) {
        float acc = linb[t];
#pragma unroll 16
        for (int k = 0; k < HIDDEN; k++)
            acc += se[k] * linW[k * NUM_CLASSES + t];
        out[g * NUM_CLASSES + t] = acc;
    }
}

extern "C" void kernel_launch(void* const* d_in, const int* in_sizes, int n_in,
                              void* d_out, int out_size) {
    const float* x     = (const float*)d_in[0];
    const int*   ei    = (const int*)d_in[1];   // [2, E] (JAX x64 off -> int32)
    const int*   batch = (const int*)d_in[2];
    const float* W0 = (const float*)d_in[3];
    const float* b0 = (const float*)d_in[4];
    const float* W1 = (const float*)d_in[5];
    const float* b1 = (const float*)d_in[6];
    const float* W2 = (const float*)d_in[7];
    const float* b2 = (const float*)d_in[8];
    const float* linW = (const float*)d_in[9];
    const float* linb = (const float*)d_in[10];
    float* out = (float*)d_out;

    const int* src = ei;            // edge_index[0]
    const int* dst = ei + N_EDGES;  // edge_index[1]

    // ---- fork-join: branch B builds CSR while branch A converts + runs GEMM0 ----
    cudaStream_t sB;
    cudaStreamCreateWithFlags(&sB, cudaStreamNonBlocking);
    cudaEvent_t evFork, evJoin;
    cudaEventCreateWithFlags(&evFork, cudaEventDisableTiming);
    cudaEventCreateWithFlags(&evJoin, cudaEventDisableTiming);

    const float* bs[3] = {b0, b1, b2};
    const int gemm_grid = (N_NODES + TC_ROWS - 1) / TC_ROWS;     // 782
    const int agg_grid = (N_NODES + AGG_NODES - 1) / AGG_NODES;  // 6250 exact

    // head on default stream, then fork
    k_zerodeg<<<(N_NODES + 255) / 256, 256>>>();
    cudaEventRecord(evFork, 0);
    cudaStreamWaitEvent(sB, evFork, 0);

    // branch B (stream sB): degree -> scan -> fill
    k_deg<<<(N_EDGES / 2 + 255) / 256, 256, 0, sB>>>(dst);
    k_scan1<<<SCAN_NBLK, SCAN_BLK, 0, sB>>>();
    k_scan3<<<SCAN_NBLK, SCAN_BLK, 0, sB>>>();
    k_fill<<<(N_EDGES + 255) / 256, 256, 0, sB>>>(src, dst);
    cudaEventRecord(evJoin, sB);

    // branch A (default stream): conversions + layer-0 GEMM
    k_init<<<(N_NODES * (HIDDEN / 2) + 255) / 256, 256>>>(x, W0, W1, W2);
    k_gemm_tc<<<gemm_grid, 256>>>(0);

    // join: agg(0) needs CSR + hw
    cudaStreamWaitEvent(0, evJoin, 0);
    k_agg<<<agg_grid, 256>>>(bs[0]);

    for (int l = 1; l < 3; l++) {
        k_gemm_tc<<<gemm_grid, 256>>>(l);
        k_agg<<<agg_grid, 256>>>(bs[l]);
    }

    k_pool<<<(N_NODES + NODES_PER_BLOCK - 1) / NODES_PER_BLOCK, 64>>>(batch);

    // Output: reference returns (logits[64,6], embedding[64,128]) -> 8576 floats.
    int write_logits = 1, write_emb = 0, emb_off = 0;
    if (out_size >= NUM_GRAPHS * (NUM_CLASSES + HIDDEN)) {
        write_emb = 1; emb_off = NUM_GRAPHS * NUM_CLASSES;
    } else if (out_size == NUM_GRAPHS * HIDDEN) {
        write_emb = 1; write_logits = 0; emb_off = 0;
    }
    k_final<<<NUM_GRAPHS, HIDDEN>>>(linW, linb, out, emb_off, write_emb, write_logits);

    cudaEventDestroy(evFork);
    cudaEventDestroy(evJoin);
    cudaStreamDestroy(sB);
}

// round 13
// speedup vs baseline: 1.3705x; 1.0726x over previous
#include <cuda_runtime.h>
#include <cuda_fp16.h>
#include <mma.h>

using namespace nvcuda;

#define N_NODES 50000
#define N_EDGES 800000
#define HIDDEN 128
#define NUM_GRAPHS 64
#define NUM_CLASSES 6

#define SCAN_BLK 256
#define SCAN_NBLK ((N_NODES + SCAN_BLK - 1) / SCAN_BLK)   // 196

// ---- scratch (static device globals; no runtime allocation) ----
__device__ __half2 g_hw2[N_NODES * (HIDDEN / 2)];   // h @ W, fp16 packed
__device__ __half2 g_h2[N_NODES * (HIDDEN / 2)];    // layer activation, fp16 packed
__device__ __half  g_Wh[3 * HIDDEN * HIDDEN];       // fp16 weights
__device__ float   g_dinv[N_NODES];
__device__ int     g_deg[N_NODES];
__device__ int     g_rowptr[N_NODES + 1];
__device__ int     g_cursor[N_NODES];
__device__ int2    g_csr[N_EDGES];                  // (src, w bits) packed
__device__ int     g_bsum[SCAN_NBLK];
__device__ float   g_pool[NUM_GRAPHS * HIDDEN];
__device__ float   g_cnt[NUM_GRAPHS];

// ---- branch-B head: zero degree array ----
__global__ void k_zerodeg() {
    int i = blockIdx.x * blockDim.x + threadIdx.x;
    if (i < N_NODES) g_deg[i] = 0;
}

// ---- branch-A: cvt x -> fp16, cvt weights -> fp16, zero pool/cnt ----
__global__ void k_init(const float* __restrict__ x, const float* __restrict__ W0,
                       const float* __restrict__ W1, const float* __restrict__ W2) {
    int i = blockIdx.x * blockDim.x + threadIdx.x;
    if (i < N_NODES * (HIDDEN / 2)) {
        float2 v = ((const float2*)x)[i];
        g_h2[i] = __floats2half2_rn(v.x, v.y);
    }
    if (i < HIDDEN * HIDDEN) {
        g_Wh[i] = __float2half(W0[i]);
        g_Wh[HIDDEN * HIDDEN + i] = __float2half(W1[i]);
        g_Wh[2 * HIDDEN * HIDDEN + i] = __float2half(W2[i]);
    }
    if (i < NUM_GRAPHS * HIDDEN) g_pool[i] = 0.f;
    if (i < NUM_GRAPHS) g_cnt[i] = 0.f;
}

// ---- degree histogram: 4 edges per thread ----
__global__ void k_deg(const int* __restrict__ dst) {
    int i = blockIdx.x * blockDim.x + threadIdx.x;
    int e0 = 4 * i;
    if (e0 + 3 < N_EDGES) {
        int4 d = ((const int4*)dst)[i];
        atomicAdd(&g_deg[d.x], 1);
        atomicAdd(&g_deg[d.y], 1);
        atomicAdd(&g_deg[d.z], 1);
        atomicAdd(&g_deg[d.w], 1);
    } else {
        for (int e = e0; e < N_EDGES; e++) atomicAdd(&g_deg[dst[e]], 1);
    }
}

// ---- scan pass 1: per-block sums of g_deg ----
__global__ void k_scan1() {
    __shared__ int wsum[SCAN_BLK / 32];
    int i = blockIdx.x * SCAN_BLK + threadIdx.x;
    int v = (i < N_NODES) ? g_deg[i] : 0;
#pragma unroll
    for (int o = 16; o > 0; o >>= 1) v += __shfl_down_sync(0xffffffffu, v, o);
    if ((threadIdx.x & 31) == 0) wsum[threadIdx.x >> 5] = v;
    __syncthreads();
    if (threadIdx.x < SCAN_BLK / 32) {
        int s = wsum[threadIdx.x];
#pragma unroll
        for (int o = SCAN_BLK / 64; o > 0; o >>= 1)
            s += __shfl_down_sync(0xffffffffu, s, o);
        if (threadIdx.x == 0) g_bsum[blockIdx.x] = s;
    }
}

// ---- scan pass 2: per-block local scan; block offset computed inline ----
__global__ void k_scan3() {
    __shared__ int wpre[SCAN_BLK / 32];
    __shared__ int s_off;
    int lane = threadIdx.x & 31;
    int wid = threadIdx.x >> 5;

    // block offset = sum of g_bsum[0 .. blockIdx.x)
    int partial = 0;
    for (int b = threadIdx.x; b < blockIdx.x; b += SCAN_BLK)
        partial += g_bsum[b];
#pragma unroll
    for (int o = 16; o > 0; o >>= 1)
        partial += __shfl_down_sync(0xffffffffu, partial, o);
    if (lane == 0) wpre[wid] = partial;
    __syncthreads();
    if (threadIdx.x == 0) {
        int s = 0;
#pragma unroll
        for (int w = 0; w < SCAN_BLK / 32; w++) s += wpre[w];
        s_off = s;
    }
    __syncthreads();

    int i = blockIdx.x * SCAN_BLK + threadIdx.x;
    int v = (i < N_NODES) ? g_deg[i] : 0;
    int x = v;
#pragma unroll
    for (int o = 1; o < 32; o <<= 1) {
        int y = __shfl_up_sync(0xffffffffu, x, o);
        if (lane >= o) x += y;
    }
    if (lane == 31) wpre[wid] = x;
    __syncthreads();
    if (wid == 0 && lane < SCAN_BLK / 32) {
        int s = wpre[lane];
#pragma unroll
        for (int o = 1; o < SCAN_BLK / 32; o <<= 1) {
            int y = __shfl_up_sync((1u << (SCAN_BLK / 32)) - 1u, s, o);
            if (lane >= o) s += y;
        }
        wpre[lane] = s;
    }
    __syncthreads();
    if (i < N_NODES) {
        int excl = (x - v) + (wid > 0 ? wpre[wid - 1] : 0) + s_off;
        g_rowptr[i] = excl;
        g_cursor[i] = excl;
        g_dinv[i] = rsqrtf((float)(v + 1));   // +1 self-loop
        if (i == 0) g_rowptr[N_NODES] = N_EDGES;
    }
}

// ---- fill CSR (packed src + weight), 2 edges per thread ----
__global__ void k_fill(const int* __restrict__ src, const int* __restrict__ dst) {
    int i = blockIdx.x * blockDim.x + threadIdx.x;
    int e0 = 2 * i;
    if (e0 + 1 < N_EDGES) {
        int2 s = ((const int2*)src)[i];
        int2 d = ((const int2*)dst)[i];
        int p0 = atomicAdd(&g_cursor[d.x], 1);
        g_csr[p0] = make_int2(s.x, __float_as_int(g_dinv[s.x] * g_dinv[d.x]));
        int p1 = atomicAdd(&g_cursor[d.y], 1);
        g_csr[p1] = make_int2(s.y, __float_as_int(g_dinv[s.y] * g_dinv[d.y]));
    } else if (e0 < N_EDGES) {
        int s = src[e0], d = dst[e0];
        int pos = atomicAdd(&g_cursor[d], 1);
        g_csr[pos] = make_int2(s, __float_as_int(g_dinv[s] * g_dinv[d]));
    }
}

// ---- tensor-core projection: hw = h @ W (fp16 in, fp32 accum, fp16 out) ----
// Block: 256 threads (8 warps) handles 128 rows x 128 cols; each warp owns
// two 16-row tiles (rt and rt+4) in its column half.
#define TC_ROWS 128
__global__ void __launch_bounds__(256) k_gemm_tc(int layer) {
    __shared__ __align__(256) char smem_raw[64 * HIDDEN * 4];  // 32 KB
    __half* sB = (__half*)smem_raw;       // phase 1: B tile 128x128 fp16
    float*  sC = (float*)smem_raw;        // phase 2: C staging 64x128 fp32 (x2 passes)
    int tid = threadIdx.x;

    const int4* Bv = (const int4*)(g_Wh + (size_t)layer * HIDDEN * HIDDEN);
    int4* sBv = (int4*)sB;
#pragma unroll
    for (int i = 0; i < 8; i++)
        sBv[tid + i * 256] = Bv[tid + i * 256];
    __syncthreads();

    int warp = tid >> 5;
    int rt = warp >> 1;       // 0..3
    int ch = warp & 1;        // 0..1
    const __half* A = (const __half*)g_h2;
    int row_block = blockIdx.x * TC_ROWS;

    wmma::fragment<wmma::accumulator, 16, 16, 16, float> c[2][4];
#pragma unroll
    for (int h = 0; h < 2; h++)
#pragma unroll
        for (int j = 0; j < 4; j++) wmma::fill_fragment(c[h][j], 0.f);

#pragma unroll
    for (int h = 0; h < 2; h++) {
        int row0 = row_block + (h * 4 + rt) * 16;
        if (row0 < N_NODES) {
#pragma unroll
            for (int k = 0; k < 8; k++) {
                wmma::fragment<wmma::matrix_a, 16, 16, 16, __half, wmma::row_major> a;
                wmma::load_matrix_sync(a, A + (size_t)row0 * HIDDEN + k * 16, HIDDEN);
#pragma unroll
                for (int j = 0; j < 4; j++) {
                    wmma::fragment<wmma::matrix_b, 16, 16, 16, __half, wmma::row_major> b;
                    wmma::load_matrix_sync(b, sB + (k * 16) * HIDDEN + ch * 64 + j * 16, HIDDEN);
                    wmma::mma_sync(c[h][j], a, b, c[h][j]);
                }
            }
        }
    }

    // two staging passes through the 64-row fp32 buffer
#pragma unroll
    for (int h = 0; h < 2; h++) {
        __syncthreads();
        int row0 = row_block + (h * 4 + rt) * 16;
        if (row0 < N_NODES) {
#pragma unroll
            for (int j = 0; j < 4; j++)
                wmma::store_matrix_sync(sC + (rt * 16) * HIDDEN + ch * 64 + j * 16,
                                        c[h][j], HIDDEN, wmma::mem_row_major);
        }
        __syncthreads();
        int half_base = row_block + h * 64;
#pragma unroll
        for (int i = 0; i < 16; i++) {
            int idx = tid + i * 256;          // half2 slot: 0..4095
            int r = idx >> 6;
            if (half_base + r < N_NODES) {
                float2 v = ((float2*)sC)[idx];
                g_hw2[(size_t)(half_base + r) * 64 + (idx & 63)] = __floats2half2_rn(v.x, v.y);
            }
        }
    }
}

// ---- fused aggregate: 1 warp per node, 8B (2x half2) per thread, unroll 8 ----
#define AGG_NODES 8
__global__ void k_agg(const float* __restrict__ bias) {
    int n = blockIdx.x * AGG_NODES + (threadIdx.x >> 5);
    int t = threadIdx.x & 31;   // uint2 slot: half2 pair (cols 4t..4t+3)
    int beg = g_rowptr[n];
    int end = g_rowptr[n + 1];
    float dv = g_dinv[n];

    const uint2* hw = (const uint2*)g_hw2;   // 32 uint2 per row
    uint2 sr = hw[(size_t)n * 32 + t];
    float2 s0 = __half22float2(*(__half2*)&sr.x);
    float2 s1 = __half22float2(*(__half2*)&sr.y);
    float n2 = dv * dv;
    float ax = n2 * s0.x, ay = n2 * s0.y;
    float az = n2 * s1.x, aw = n2 * s1.y;

    int j = beg;
    for (; j + 8 <= end; j += 8) {
        int2 ed[8];
        uint2 rr[8];
#pragma unroll
        for (int u = 0; u < 8; u++) ed[u] = g_csr[j + u];
#pragma unroll
        for (int u = 0; u < 8; u++) rr[u] = hw[(size_t)ed[u].x * 32 + t];
#pragma unroll
        for (int u = 0; u < 8; u++) {
            float w = __int_as_float(ed[u].y);
            float2 a = __half22float2(*(__half2*)&rr[u].x);
            float2 b = __half22float2(*(__half2*)&rr[u].y);
            ax += w * a.x; ay += w * a.y; az += w * b.x; aw += w * b.y;
        }
    }
    for (; j < end; j++) {
        int2 e = g_csr[j];
        float w = __int_as_float(e.y);
        uint2 r = hw[(size_t)e.x * 32 + t];
        float2 a = __half22float2(*(__half2*)&r.x);
        float2 b = __half22float2(*(__half2*)&r.y);
        ax += w * a.x; ay += w * a.y; az += w * b.x; aw += w * b.y;
    }
    float4 b4 = ((const float4*)bias)[t];
    uint2 outp;
    *(__half2*)&outp.x = __floats2half2_rn(fmaxf(ax + b4.x, 0.f), fmaxf(ay + b4.y, 0.f));
    *(__half2*)&outp.y = __floats2half2_rn(fmaxf(az + b4.z, 0.f), fmaxf(aw + b4.w, 0.f));
    ((uint2*)g_h2)[(size_t)n * 32 + t] = outp;
}

// ---- pooling: run-length accumulate over sorted batch ids (fp16 h, fp32 acc) ----
#define NODES_PER_BLOCK 32
__global__ void k_pool(const int* __restrict__ batch) {
    int n0 = blockIdx.x * NODES_PER_BLOCK;
    if (n0 >= N_NODES) return;
    int t = threadIdx.x;  // 0..63, half2 column pair
    int cur = batch[n0];
    float ax = 0.f, ay = 0.f;
    int run = 0;
    for (int r = 0; r < NODES_PER_BLOCK; r++) {
        int n = n0 + r;
        if (n >= N_NODES) break;
        int bg = batch[n];
        if (bg != cur) {
            atomicAdd(&g_pool[cur * HIDDEN + 2 * t], ax);
            atomicAdd(&g_pool[cur * HIDDEN + 2 * t + 1], ay);
            if (t == 0) atomicAdd(&g_cnt[cur], (float)run);
            ax = 0.f; ay = 0.f; run = 0; cur = bg;
        }
        float2 v = __half22float2(g_h2[(size_t)n * 64 + t]);
        ax += v.x; ay += v.y;
        run++;
    }
    atomicAdd(&g_pool[cur * HIDDEN + 2 * t], ax);
    atomicAdd(&g_pool[cur * HIDDEN + 2 * t + 1], ay);
    if (t == 0) atomicAdd(&g_cnt[cur], (float)run);
}

// ---- mean + linear head, write outputs ----
__global__ void k_final(const float* __restrict__ linW, const float* __restrict__ linb,
                        float* __restrict__ out, int emb_off,
                        int write_emb, int write_logits) {
    int g = blockIdx.x;
    int t = threadIdx.x;  // 128
    float c = fmaxf(g_cnt[g], 1.f);
    float e = g_pool[g * HIDDEN + t] / c;
    __shared__ float se[HIDDEN];
    se[t] = e;
    if (write_emb) out[emb_off + g * HIDDEN + t] = e;
    __syncthreads();
    if (write_logits && t < NUM_CLASSES) {
        float acc = linb[t];
#pragma unroll 16
        for (int k = 0; k < HIDDEN; k++)
            acc += se[k] * linW[k * NUM_CLASSES + t];
        out[g * NUM_CLASSES + t] = acc;
    }
}

extern "C" void kernel_launch(void* const* d_in, const int* in_sizes, int n_in,
                              void* d_out, int out_size) {
    const float* x     = (const float*)d_in[0];
    const int*   ei    = (const int*)d_in[1];   // [2, E] (JAX x64 off -> int32)
    const int*   batch = (const int*)d_in[2];
    const float* W0 = (const float*)d_in[3];
    const float* b0 = (const float*)d_in[4];
    const float* W1 = (const float*)d_in[5];
    const float* b1 = (const float*)d_in[6];
    const float* W2 = (const float*)d_in[7];
    const float* b2 = (const float*)d_in[8];
    const float* linW = (const float*)d_in[9];
    const float* linb = (const float*)d_in[10];
    float* out = (float*)d_out;

    const int* src = ei;            // edge_index[0]
    const int* dst = ei + N_EDGES;  // edge_index[1]

    // ---- fork-join: branch B builds CSR while branch A converts + runs GEMM0 ----
    cudaStream_t sB;
    cudaStreamCreateWithFlags(&sB, cudaStreamNonBlocking);
    cudaEvent_t evFork, evJoin;
    cudaEventCreateWithFlags(&evFork, cudaEventDisableTiming);
    cudaEventCreateWithFlags(&evJoin, cudaEventDisableTiming);

    const float* bs[3] = {b0, b1, b2};
    const int gemm_grid = (N_NODES + TC_ROWS - 1) / TC_ROWS;     // 391
    const int agg_grid = (N_NODES + AGG_NODES - 1) / AGG_NODES;  // 6250 exact

    // head on default stream, then fork
    k_zerodeg<<<(N_NODES + 255) / 256, 256>>>();
    cudaEventRecord(evFork, 0);
    cudaStreamWaitEvent(sB, evFork, 0);

    // branch B (stream sB): degree -> scan -> fill
    k_deg<<<(N_EDGES / 4 + 255) / 256, 256, 0, sB>>>(dst);
    k_scan1<<<SCAN_NBLK, SCAN_BLK, 0, sB>>>();
    k_scan3<<<SCAN_NBLK, SCAN_BLK, 0, sB>>>();
    k_fill<<<(N_EDGES / 2 + 255) / 256, 256, 0, sB>>>(src, dst);
    cudaEventRecord(evJoin, sB);

    // branch A (default stream): conversions + layer-0 GEMM
    k_init<<<(N_NODES * (HIDDEN / 2) + 255) / 256, 256>>>(x, W0, W1, W2);
    k_gemm_tc<<<gemm_grid, 256>>>(0);

    // join: agg(0) needs CSR + hw
    cudaStreamWaitEvent(0, evJoin, 0);
    k_agg<<<agg_grid, 256>>>(bs[0]);

    for (int l = 1; l < 3; l++) {
        k_gemm_tc<<<gemm_grid, 256>>>(l);
        k_agg<<<agg_grid, 256>>>(bs[l]);
    }

    k_pool<<<(N_NODES + NODES_PER_BLOCK - 1) / NODES_PER_BLOCK, 64>>>(batch);

    // Output: reference returns (logits[64,6], embedding[64,128]) -> 8576 floats.
    int write_logits = 1, write_emb = 0, emb_off = 0;
    if (out_size >= NUM_GRAPHS * (NUM_CLASSES + HIDDEN)) {
        write_emb = 1; emb_off = NUM_GRAPHS * NUM_CLASSES;
    } else if (out_size == NUM_GRAPHS * HIDDEN) {
        write_emb = 1; write_logits = 0; emb_off = 0;
    }
    k_final<<<NUM_GRAPHS, HIDDEN>>>(linW, linb, out, emb_off, write_emb, write_logits);

    cudaEventDestroy(evFork);
    cudaEventDestroy(evJoin);
    cudaStreamDestroy(sB);
}